// round 3
// baseline (speedup 1.0000x reference)
#include <cuda_runtime.h>
#include <cstdint>

#define BB 16
#define SS 2048
#define DD 256
#define LL 4
#define GD 1024
#define NF 6
#define NROW (BB*SS)

typedef unsigned long long u64;

// ---------------- static scratch (allocation-free) ----------------
__device__ float g_h[NROW * DD];          // residual stream
__device__ float g_gx[(size_t)NROW * GD]; // per-layer preactivations
__device__ float g_mu[NROW];
__device__ float g_rstd[NROW];
__device__ float g_Wp[DD * GD];           // gamma-folded Wx
__device__ float g_u[GD];
__device__ float g_v[GD];
__device__ float g_hbuf[2 * BB * DD];     // double-buffered hidden state
__device__ unsigned int g_flags[BB * SS];

// ---------------- f32x2 helpers ----------------
__device__ __forceinline__ void fma2(u64 &d, u64 a, u64 b) {
    asm("fma.rn.f32x2 %0,%1,%2,%0;" : "+l"(d) : "l"(a), "l"(b));
}
__device__ __forceinline__ u64 pk(float x, float y) {
    u64 r; asm("mov.b64 %0,{%1,%2};" : "=l"(r) : "f"(x), "f"(y)); return r;
}
__device__ __forceinline__ void upk(u64 v, float &x, float &y) {
    asm("mov.b64 {%0,%1},%2;" : "=f"(x), "=f"(y) : "l"(v));
}

// ---------------- kernels ----------------
__global__ void k_clear() {
    g_flags[blockIdx.x * 256 + threadIdx.x] = 0u;
}

__global__ void k_inproj(const float* __restrict__ x, const float* __restrict__ tf,
                         const float* __restrict__ inW, const float* __restrict__ inb) {
    int row = blockIdx.x, d = threadIdx.x;
    float acc = inb[d] + __ldg(x + row) * inW[d];
#pragma unroll
    for (int f = 0; f < NF; f++)
        acc += __ldg(tf + (size_t)row * NF + f) * inW[(1 + f) * DD + d];
    g_h[(size_t)row * DD + d] = acc;
}

__global__ void k_stats() {
    int row = blockIdx.x * 8 + (threadIdx.x >> 5);
    int lane = threadIdx.x & 31;
    const float* p = g_h + (size_t)row * DD;
    float s = 0.f, s2 = 0.f;
#pragma unroll
    for (int i = lane; i < DD; i += 32) { float v = p[i]; s += v; s2 += v * v; }
#pragma unroll
    for (int o = 16; o > 0; o >>= 1) {
        s  += __shfl_xor_sync(0xffffffffu, s, o);
        s2 += __shfl_xor_sync(0xffffffffu, s2, o);
    }
    if (lane == 0) {
        float mu = s * (1.f / DD);
        float var = s2 * (1.f / DD) - mu * mu;
        g_mu[row] = mu;
        g_rstd[row] = rsqrtf(var + 1e-5f);
    }
}

__global__ void k_fold(const float* __restrict__ Wx, const float* __restrict__ lng,
                       const float* __restrict__ lnb, const float* __restrict__ bg, int l) {
    int j = blockIdx.x * 256 + threadIdx.x;
    const float* W = Wx + (size_t)l * DD * GD;
    float u = 0.f, v = 0.f;
    for (int k = 0; k < DD; k++) {
        float w  = W[(size_t)k * GD + j];
        float gk = lng[l * DD + k];
        g_Wp[(size_t)k * GD + j] = w * gk;
        u += gk * w;
        v += lnb[l * DD + k] * w;
    }
    g_u[j] = u;
    g_v[j] = v + bg[(size_t)l * GD + j];
}

#define PA 260
#define PB 258
#define GEMM_SMEM ((64 * PA + 128 * PB) * 4)   // 198,656 bytes

// As: [64 rows][PA] (row-major over k) ; Bs: [128 cols][PB] (col-major over k)
__global__ void __launch_bounds__(256) k_gemm() {
    extern __shared__ float sm[];
    float* As = sm;               // 64*PA
    float* Bs = sm + 64 * PA;     // 128*PB
    int m0 = blockIdx.x * 64;
    int n0 = blockIdx.y * 128;

    for (int idx = threadIdx.x; idx < 64 * 64; idx += 256) { // A: 64 rows x 256 k (float4)
        int r = idx >> 6, k4 = (idx & 63) << 2;
        float4 vv = *(const float4*)(g_h + (size_t)(m0 + r) * DD + k4);
        *(float4*)(As + r * PA + k4) = vv;
    }
    for (int idx = threadIdx.x; idx < 128 * DD; idx += 256) { // B: transpose into [col][k]
        int k = idx >> 7, c = idx & 127;
        Bs[c * PB + k] = g_Wp[(size_t)k * GD + n0 + c];
    }
    __syncthreads();

    int tc = threadIdx.x & 15;
    int tr = threadIdx.x >> 4;
    int r0 = tr * 4;

    u64 acc[4][8];
#pragma unroll
    for (int r = 0; r < 4; r++)
#pragma unroll
        for (int j = 0; j < 8; j++) acc[r][j] = 0ull;

#pragma unroll 4
    for (int k = 0; k < DD; k += 2) {
        u64 a2[4], b2[8];
#pragma unroll
        for (int r = 0; r < 4; r++) a2[r] = *(const u64*)(As + (r0 + r) * PA + k);
#pragma unroll
        for (int j = 0; j < 8; j++) b2[j] = *(const u64*)(Bs + (tc + 16 * j) * PB + k);
#pragma unroll
        for (int r = 0; r < 4; r++)
#pragma unroll
            for (int j = 0; j < 8; j++) fma2(acc[r][j], a2[r], b2[j]);
    }

#pragma unroll
    for (int r = 0; r < 4; r++) {
        int row = m0 + r0 + r;
        float rs = g_rstd[row];
        float rm = rs * g_mu[row];
#pragma unroll
        for (int j = 0; j < 8; j++) {
            int colg = n0 + tc + 16 * j;
            float xe, yo; upk(acc[r][j], xe, yo);
            g_gx[(size_t)row * GD + colg] = rs * (xe + yo) - rm * g_u[colg] + g_v[colg];
        }
    }
}

// sLSTM recurrence: grid (8 col-slices, 16 batches), Wh slice in registers.
__global__ void __launch_bounds__(256, 1) k_rec(const float* __restrict__ Wh, int l) {
    int c = blockIdx.x, b = blockIdx.y;
    int tid = threadIdx.x;
    int col = tid & 127;            // g*32 + dl
    int khalf = tid >> 7;           // 0/1
    int g = col >> 5, dl = col & 31;
    int gcol = g * DD + c * 32 + dl;
    int k0 = khalf * 128;

    const float* W = Wh + (size_t)l * DD * GD;
    u64 wq[64];
#pragma unroll
    for (int i = 0; i < 64; i++) {
        float w0 = __ldg(W + (size_t)(k0 + 2 * i)     * GD + gcol);
        float w1 = __ldg(W + (size_t)(k0 + 2 * i + 1) * GD + gcol);
        wq[i] = pk(w0, w1);
    }

    __shared__ __align__(16) float hsm[DD];
    __shared__ float part[128];
    __shared__ float gbuf[128];

    unsigned int* flags = g_flags + (size_t)b * SS;
    const float* gxp = g_gx + (size_t)b * SS * GD;
    float* hres = g_h + (size_t)b * SS * DD;

    float st_c = 0.f, st_n = 0.f, st_m = 0.f;

    for (int s = 0; s < SS; s++) {
        float gxv = 0.f, hrv = 0.f;
        if (tid < 128) gxv = __ldg(gxp + (size_t)s * GD + gcol);
        if (tid < 32)  hrv = hres[(size_t)s * DD + c * 32 + tid];

        if (s > 0) {
            if (tid == 0) {
                volatile unsigned int* fp = (volatile unsigned int*)(flags + (s - 1));
                while (*fp < 8u) {}
            }
            __syncthreads();
            hsm[tid] = __ldcg(g_hbuf + ((s - 1) & 1) * BB * DD + b * DD + tid);
        } else {
            hsm[tid] = 0.f;
        }
        __syncthreads();

        // dot(h_prev[k0:k0+128], Wh[k0:k0+128, gcol])
        u64 acc = 0ull;
        const ulonglong2* h4 = (const ulonglong2*)(hsm + k0);
#pragma unroll
        for (int i = 0; i < 32; i++) {
            ulonglong2 hv = h4[i];
            fma2(acc, hv.x, wq[2 * i]);
            fma2(acc, hv.y, wq[2 * i + 1]);
        }
        float lo, hi; upk(acc, lo, hi);
        float dot = lo + hi;

        if (khalf) part[col] = dot;
        __syncthreads();
        if (tid < 128) gbuf[col] = gxv + dot + part[col];
        __syncthreads();

        if (tid < 32) {
            float it = gbuf[tid];
            float ft = gbuf[32 + tid];
            float zt = gbuf[64 + tid];
            float ot = gbuf[96 + tid];
            float mn = fmaxf(ft + st_m, it);
            float ip = __expf(it - mn);
            float fp2 = __expf(ft + st_m - mn);
            st_c = fp2 * st_c + ip * tanhf(zt);
            st_n = fp2 * st_n + ip;
            st_m = mn;
            float hv = (1.f / (1.f + __expf(-ot))) * st_c / fmaxf(fabsf(st_n), 1.f);
            g_hbuf[(s & 1) * BB * DD + b * DD + c * 32 + tid] = hv;
            hres[(size_t)s * DD + c * 32 + tid] = hrv + hv;
            __threadfence();
        }
        __syncthreads();
        if (tid == 0) atomicAdd(flags + s, 1u);
    }
}

__global__ void k_out(const float* __restrict__ fcW, const float* __restrict__ fcb,
                      float* __restrict__ out) {
    int b = blockIdx.x, t = threadIdx.x;
    __shared__ float red[256];
    red[t] = g_h[((size_t)b * SS + SS - 1) * DD + t] * fcW[t];
    __syncthreads();
    for (int o = 128; o > 0; o >>= 1) {
        if (t < o) red[t] += red[t + o];
        __syncthreads();
    }
    if (t == 0) out[b] = red[0] + fcb[0];
}

// ---------------- host ----------------
extern "C" void kernel_launch(void* const* d_in, const int* in_sizes, int n_in,
                              void* d_out, int out_size) {
    const float* x    = (const float*)d_in[0];
    const float* tf   = (const float*)d_in[1];
    const float* inW  = (const float*)d_in[2];
    const float* inb  = (const float*)d_in[3];
    const float* lng  = (const float*)d_in[4];
    const float* lnb  = (const float*)d_in[5];
    const float* Wx   = (const float*)d_in[6];
    const float* Wh   = (const float*)d_in[7];
    const float* bg   = (const float*)d_in[8];
    const float* fcW  = (const float*)d_in[9];
    const float* fcb  = (const float*)d_in[10];
    float* out = (float*)d_out;

    cudaFuncSetAttribute(k_gemm, cudaFuncAttributeMaxDynamicSharedMemorySize, GEMM_SMEM);

    k_inproj<<<NROW, 256>>>(x, tf, inW, inb);
    for (int l = 0; l < LL; l++) {
        k_stats<<<NROW / 8, 256>>>();
        k_fold<<<4, 256>>>(Wx, lng, lnb, bg, l);
        k_gemm<<<dim3(NROW / 64, GD / 128), 256, GEMM_SMEM>>>();
        k_clear<<<BB * SS / 256, 256>>>();
        k_rec<<<dim3(8, BB), 256>>>(Wh, l);
    }
    k_out<<<BB, 256>>>(fcW, fcb, out);
}